// round 3
// baseline (speedup 1.0000x reference)
#include <cuda_runtime.h>
#include <cuda_bf16.h>

// SepConv: out[b,c,i,j] = sum_{u,v} img[b,c,i+u,j+v] * vert[b,u,i,j] * hori[b,v,i,j]
// Shapes: img[8,3,512,512], hori[8,13,500,500], vert[8,13,500,500], out[8,3,500,500]
// Factorized: out = sum_u vert[u] * (sum_v hori[v] * img[i+u, j+v])
// R3: one channel per thread (block 32x4x3 = 384 thr) -> small reg footprint,
//     24 warps/SM. hori/vert reads dedup across channel-threads in L1.

#define KSZ 13
#define CC  3
#define WW  512
#define HH  512
#define WO  500
#define HO  500

#define TXQ 32                     // j-groups; each thread covers 4 j
#define TYR 4                      // output rows per block
#define JW  4
#define JBLK (TXQ * JW)            // 128 output columns per block
#define TILE_ROWS (TYR + KSZ - 1)  // 16 img rows
#define TILE_Q   36                // float4 per tile row (144 floats >= 128+15)

__global__ __launch_bounds__(TXQ * TYR * CC, 2)
void sepconv_kernel(const float* __restrict__ img,
                    const float* __restrict__ hori,
                    const float* __restrict__ vert,
                    float* __restrict__ out) {
    __shared__ float4 s[CC][TILE_ROWS][TILE_Q];

    const int b  = blockIdx.z;
    const int j0 = blockIdx.x * JBLK;
    const int i0 = blockIdx.y * TYR;
    const int tx = threadIdx.x;        // j group
    const int ry = threadIdx.y;        // row within block
    const int cz = threadIdx.z;        // channel
    const int tid = (cz * TYR + ry) * TXQ + tx;
    const int NT  = TXQ * TYR * CC;    // 384

    // ---- cooperative load of the img tile (3 channels, 16 rows, 144 cols) ----
    const int NQ = CC * TILE_ROWS * TILE_Q;   // 1728 float4
    for (int f = tid; f < NQ; f += NT) {
        int c   = f / (TILE_ROWS * TILE_Q);
        int rem = f - c * (TILE_ROWS * TILE_Q);
        int r   = rem / TILE_Q;
        int q   = rem - r * TILE_Q;
        int gx  = i0 + r;                       // always <= 511 (grid exact in i)
        int gy  = j0 + 4 * q;
        const float* base = img + (((size_t)b * CC + c) * WW + gx) * HH;
        float4 val;
        if (gy + 3 <= HH - 1) {
            val = *(const float4*)(base + gy);
        } else {
            int y0 = gy     < HH ? gy     : HH - 1;
            int y1 = gy + 1 < HH ? gy + 1 : HH - 1;
            int y2 = gy + 2 < HH ? gy + 2 : HH - 1;
            int y3 = gy + 3 < HH ? gy + 3 : HH - 1;
            val = make_float4(base[y0], base[y1], base[y2], base[y3]);
        }
        s[c][r][q] = val;
    }
    __syncthreads();

    const int i = i0 + ry;                // always < 500 (125*4 = 500)
    const int j = j0 + JW * tx;
    if (j >= HO) return;                  // HO%4==0 -> whole float4 valid when j<HO

    // ---- per-pixel horizontal weights in registers (13 x float4) ----
    float4 hw[KSZ];
    const float* hbase = hori + (((size_t)b * KSZ) * WO + i) * HO + j;
    #pragma unroll
    for (int v = 0; v < KSZ; v++)
        hw[v] = *(const float4*)(hbase + (size_t)v * WO * HO);

    float4 acc = make_float4(0.f, 0.f, 0.f, 0.f);
    const float* vbase = vert + (((size_t)b * KSZ) * WO + i) * HO + j;

    #pragma unroll
    for (int u = 0; u < KSZ; u++) {
        float4 vw = *(const float4*)(vbase + (size_t)u * WO * HO);

        // 16-float register window: columns j .. j+15 of img row i+u, channel cz
        const float4* rowp = &s[cz][ry + u][0] + tx;
        float w[16];
        #pragma unroll
        for (int k = 0; k < 4; k++) {
            float4 t4 = rowp[k];
            w[4*k+0] = t4.x; w[4*k+1] = t4.y; w[4*k+2] = t4.z; w[4*k+3] = t4.w;
        }
        float r0 = 0.f, r1 = 0.f, r2 = 0.f, r3 = 0.f;
        #pragma unroll
        for (int v = 0; v < KSZ; v++) {
            r0 = fmaf(hw[v].x, w[v + 0], r0);
            r1 = fmaf(hw[v].y, w[v + 1], r1);
            r2 = fmaf(hw[v].z, w[v + 2], r2);
            r3 = fmaf(hw[v].w, w[v + 3], r3);
        }
        acc.x = fmaf(vw.x, r0, acc.x);
        acc.y = fmaf(vw.y, r1, acc.y);
        acc.z = fmaf(vw.z, r2, acc.z);
        acc.w = fmaf(vw.w, r3, acc.w);
    }

    float* obase = out + (((size_t)b * CC + cz) * WO + i) * HO + j;
    *(float4*)obase = acc;
}

extern "C" void kernel_launch(void* const* d_in, const int* in_sizes, int n_in,
                              void* d_out, int out_size) {
    const float* img  = (const float*)d_in[0];
    const float* hori = (const float*)d_in[1];
    const float* vert = (const float*)d_in[2];
    float* out = (float*)d_out;

    const int B = 8;
    dim3 block(TXQ, TYR, CC);               // 384 threads
    dim3 grid((HO + JBLK - 1) / JBLK,       // 4
              WO / TYR,                     // 125 (exact)
              B);                           // 8
    sepconv_kernel<<<grid, block>>>(img, hori, vert, out);
}

// round 4
// speedup vs baseline: 1.4787x; 1.4787x over previous
#include <cuda_runtime.h>
#include <cuda_bf16.h>

// SepConv: out[b,c,i,j] = sum_{u,v} img[b,c,i+u,j+v] * vert[b,u,i,j] * hori[b,v,i,j]
// Shapes: img[8,3,512,512], hori[8,13,500,500], vert[8,13,500,500], out[8,3,500,500]
// Factorized: out = sum_u vert[u] * (sum_v hori[v] * img[i+u, j+v])
// R4: back to R1 geometry (best so far), inner math converted to packed
//     fma.rn.f32x2 (sm_103a FFMA2) -> halves fma-pipe issue cycles.
//     Even taps use pairs aligned straight out of LDS.128; odd taps use 7
//     packed shifted pairs (alu-pipe movs, overlap with fma pipe).

#define KSZ 13
#define CC  3
#define WW  512
#define HH  512
#define WO  500
#define HO  500

#define TX  32                 // thread-groups in j; each thread covers 4 j
#define TY  8                  // output rows per block
#define JBLK (TX * 4)          // 128 output columns per block
#define TILE_ROWS (TY + KSZ - 1)   // 20 img rows
#define TILE_Q   36                // float4 per tile row (144 floats >= 128+15+1)

typedef unsigned long long ull;

__device__ __forceinline__ void fma2(ull& d, ull a, ull b) {
    asm("fma.rn.f32x2 %0, %1, %2, %0;" : "+l"(d) : "l"(a), "l"(b));
}
__device__ __forceinline__ ull pk(float a, float b) {
    ull r; asm("mov.b64 %0, {%1, %2};" : "=l"(r) : "f"(a), "f"(b)); return r;
}
__device__ __forceinline__ float2 unpk(ull a) {
    float2 r; asm("mov.b64 {%0, %1}, %2;" : "=f"(r.x), "=f"(r.y) : "l"(a)); return r;
}

__global__ __launch_bounds__(TX * TY, 2)
void sepconv_kernel(const float* __restrict__ img,
                    const float* __restrict__ hori,
                    const float* __restrict__ vert,
                    float* __restrict__ out) {
    __shared__ float4 s[CC][TILE_ROWS][TILE_Q];

    const int b  = blockIdx.z;
    const int j0 = blockIdx.x * JBLK;
    const int i0 = blockIdx.y * TY;
    const int tx = threadIdx.x, ty = threadIdx.y;
    const int tid = ty * TX + tx;

    // ---- cooperative load of the img tile (3 channels, 20 rows, 144 cols) ----
    const int NQ = CC * TILE_ROWS * TILE_Q;   // 2160 float4
    for (int f = tid; f < NQ; f += TX * TY) {
        int c   = f / (TILE_ROWS * TILE_Q);
        int rem = f - c * (TILE_ROWS * TILE_Q);
        int r   = rem / TILE_Q;
        int q   = rem - r * TILE_Q;
        int gx  = i0 + r; if (gx > WW - 1) gx = WW - 1;   // clamped rows feed only invalid outs
        int gy  = j0 + 4 * q;
        const float* base = img + (((size_t)b * CC + c) * WW + gx) * HH;
        float4 val;
        if (gy + 3 <= HH - 1) {
            val = *(const float4*)(base + gy);
        } else {
            int y0 = gy     < HH ? gy     : HH - 1;
            int y1 = gy + 1 < HH ? gy + 1 : HH - 1;
            int y2 = gy + 2 < HH ? gy + 2 : HH - 1;
            int y3 = gy + 3 < HH ? gy + 3 : HH - 1;
            val = make_float4(base[y0], base[y1], base[y2], base[y3]);
        }
        s[c][r][q] = val;
    }
    __syncthreads();

    const int i = i0 + ty;
    const int j = j0 + 4 * tx;
    if (i >= WO || j >= HO) return;   // no further barriers below; HO%4==0 so float4 valid

    // ---- per-pixel horizontal weights as packed pairs: hw2[v] = {(hx,hy),(hz,hw)} ----
    ulonglong2 hw2[KSZ];
    const float* hbase = hori + (((size_t)b * KSZ) * WO + i) * HO + j;
    #pragma unroll
    for (int v = 0; v < KSZ; v++)
        hw2[v] = *(const ulonglong2*)(hbase + (size_t)v * WO * HO);

    ull acc01[CC], acc23[CC];
    #pragma unroll
    for (int c = 0; c < CC; c++) { acc01[c] = 0ull; acc23[c] = 0ull; }

    const float* vbase = vert + (((size_t)b * KSZ) * WO + i) * HO + j;

    #pragma unroll
    for (int u = 0; u < KSZ; u++) {
        ulonglong2 vw2 = *(const ulonglong2*)(vbase + (size_t)u * WO * HO);

        #pragma unroll
        for (int c = 0; c < CC; c++) {
            // 16-float window (cols j..j+15 of img row i+u) as 8 aligned pairs
            const ulonglong2* rp = (const ulonglong2*)(&s[c][ty + u][0] + tx);
            ulonglong2 q0 = rp[0], q1 = rp[1], q2 = rp[2], q3 = rp[3];
            ull e[8] = { q0.x, q0.y, q1.x, q1.y, q2.x, q2.y, q3.x, q3.y };

            // shifted (odd-start) pairs o[m] = (w[2m+1], w[2m+2]), m=0..6
            float2 f0 = unpk(e[0]), f1 = unpk(e[1]), f2 = unpk(e[2]), f3 = unpk(e[3]);
            float2 f4 = unpk(e[4]), f5 = unpk(e[5]), f6 = unpk(e[6]), f7 = unpk(e[7]);
            ull o[7] = { pk(f0.y, f1.x), pk(f1.y, f2.x), pk(f2.y, f3.x),
                         pk(f3.y, f4.x), pk(f4.y, f5.x), pk(f5.y, f6.x),
                         pk(f6.y, f7.x) };

            ull r01 = 0ull, r23 = 0ull;
            #pragma unroll
            for (int v = 0; v < KSZ; v++) {
                ull d01 = (v & 1) ? o[(v - 1) >> 1] : e[v >> 1];
                ull d23 = (v & 1) ? o[(v + 1) >> 1] : e[(v >> 1) + 1];
                fma2(r01, hw2[v].x, d01);
                fma2(r23, hw2[v].y, d23);
            }
            fma2(acc01[c], vw2.x, r01);
            fma2(acc23[c], vw2.y, r23);
        }
    }

    #pragma unroll
    for (int c = 0; c < CC; c++) {
        float* obase = out + (((size_t)b * CC + c) * WO + i) * HO + j;
        *(ulonglong2*)obase = make_ulonglong2(acc01[c], acc23[c]);
    }
}

extern "C" void kernel_launch(void* const* d_in, const int* in_sizes, int n_in,
                              void* d_out, int out_size) {
    const float* img  = (const float*)d_in[0];
    const float* hori = (const float*)d_in[1];
    const float* vert = (const float*)d_in[2];
    float* out = (float*)d_out;

    const int B = 8;
    dim3 block(TX, TY);                     // 256 threads
    dim3 grid((HO + JBLK - 1) / JBLK,       // 4
              (WO + TY - 1) / TY,           // 63
              B);                           // 8
    sepconv_kernel<<<grid, block>>>(img, hori, vert, out);
}